// round 9
// baseline (speedup 1.0000x reference)
#include <cuda_runtime.h>

// GCN: 250K nodes, 4M edges, F 1->16->16->4. edge_index is int32.
// Bucketed counting-sort CSR build + register-recompute layer 2:
//   k_init  : zero 245 bucket cursors
//   k_passA : scatter (row,col) 8B/edge into coarse bucket col>>10
//             (hot per-bucket atomics are L2-aggregated => ~1 random op/edge)
//   k_passB : one block per bucket: smem histogram over 1024 local targets,
//             smem scan, smem place, coalesced CSR copy-out; also writes
//             per-node {start,deg} and p = x * rsqrt(deg+1)
//   k_layer1: 4 lanes/node gather p -> g_n1 = {agg1, dinv}
//   k_layer2: 4 lanes/node gather float2 {agg1,dinv} (8B/edge) and recompute
//             q[j] = relu(agg1*W1[j]+b1[j])*dinv in registers; W2/Wfc head
//             butterfly-reduced across the 4 lanes.

static constexpr int NN    = 250000;
static constexpr int BSH   = 10;                  // bucket = col >> 10
static constexpr int BNODE = 1 << BSH;            // 1024 nodes per bucket
static constexpr int NB    = (NN + BNODE - 1) / BNODE;   // 245
static constexpr int CAPB  = 20480;               // bucket capacity (mean 16384, +32 sigma)

__device__ int    g_bcnt[NB];           // bucket cursors
__device__ int2   g_bkt[NB * CAPB];     // staged edges (row, col) per bucket
__device__ int    g_srcs[NB * CAPB];    // CSR source ids (coalesced-written)
__device__ int2   g_nfo[NN];            // per node {start, deg}
__device__ float  g_p[NN];              // x * dinv
__device__ float2 g_n1[NN];             // {agg1, dinv}

__global__ void k_init() {
    int t = blockIdx.x * blockDim.x + threadIdx.x;
    if (t < NB) g_bcnt[t] = 0;
}

// Coarse scatter: 4 edges/thread. One random 8B store per edge; cursor
// atomics hit only 245 hot addresses (cheap, L2-aggregated).
__global__ void k_passA(const int4* __restrict__ row4,
                        const int4* __restrict__ col4, int E4) {
    int e = blockIdx.x * blockDim.x + threadIdx.x;
    if (e >= E4) return;
    int4 r = row4[e];
    int4 c = col4[e];
    int b0 = c.x >> BSH, b1 = c.y >> BSH, b2 = c.z >> BSH, b3 = c.w >> BSH;
    int p0 = atomicAdd(&g_bcnt[b0], 1);
    int p1 = atomicAdd(&g_bcnt[b1], 1);
    int p2 = atomicAdd(&g_bcnt[b2], 1);
    int p3 = atomicAdd(&g_bcnt[b3], 1);
    if (p0 < CAPB) g_bkt[b0 * CAPB + p0] = make_int2(r.x, c.x);
    if (p1 < CAPB) g_bkt[b1 * CAPB + p1] = make_int2(r.y, c.y);
    if (p2 < CAPB) g_bkt[b2 * CAPB + p2] = make_int2(r.z, c.z);
    if (p3 < CAPB) g_bkt[b3 * CAPB + p3] = make_int2(r.w, c.w);
}

// Per-bucket CSR build entirely in smem. blockDim = 1024, gridDim = NB.
// dyn smem: s_deg[1024] | s_off[1024] | s_wsum[32] | s_src[CAPB]
__global__ void k_passB(const float* __restrict__ x, int N) {
    extern __shared__ int sm[];
    int* s_deg  = sm;
    int* s_off  = sm + 1024;
    int* s_wsum = sm + 2048;
    int* s_src  = sm + 2080;

    int b  = blockIdx.x;
    int t  = threadIdx.x;
    int n0 = b << BSH;
    int cb = min(g_bcnt[b], CAPB);
    const int2* bkt = &g_bkt[b * CAPB];

    s_deg[t] = 0;
    __syncthreads();

    // histogram over local targets
    for (int i = t; i < cb; i += 1024)
        atomicAdd(&s_deg[bkt[i].y & (BNODE - 1)], 1);
    __syncthreads();

    // exclusive scan of s_deg (1024 = 32 warps x 32 lanes)
    int v = s_deg[t];
    int lane = t & 31;
    int incl = v;
    #pragma unroll
    for (int d = 1; d < 32; d <<= 1) {
        int u = __shfl_up_sync(0xffffffffu, incl, d);
        if (lane >= d) incl += u;
    }
    if (lane == 31) s_wsum[t >> 5] = incl;
    __syncthreads();
    if (t < 32) {
        int w = s_wsum[t];
        int wi = w;
        #pragma unroll
        for (int d = 1; d < 32; d <<= 1) {
            int u = __shfl_up_sync(0xffffffffu, wi, d);
            if (t >= d) wi += u;
        }
        s_wsum[t] = wi - w;  // exclusive
    }
    __syncthreads();
    int excl = incl - v + s_wsum[t >> 5];
    s_off[t] = excl;

    // per-node metadata + p (before s_off is consumed as a cursor)
    int n = n0 + t;
    if (n < N) {
        g_nfo[n] = make_int2(b * CAPB + excl, v);
        g_p[n] = x[n] * rsqrtf((float)(v + 1));
    }
    __syncthreads();

    // place into smem (s_off doubles as cursor), then coalesced copy-out
    for (int i = t; i < cb; i += 1024) {
        int2 e = bkt[i];
        int pos = atomicAdd(&s_off[e.y & (BNODE - 1)], 1);
        s_src[pos] = e.x;
    }
    __syncthreads();
    int* dst = &g_srcs[b * CAPB];
    for (int i = t; i < cb; i += 1024)
        dst[i] = s_src[i];
}

// Layer 1, 4 lanes/node: agg1 = dinv*(p[n] + sum p[neigh]); store {agg1,dinv}.
__global__ void k_layer1(int N) {
    int t = threadIdx.x;
    int n = blockIdx.x * (blockDim.x >> 2) + (t >> 2);
    int lane = t & 3;
    if (n >= N) return;
    int2 fo = g_nfo[n];
    const int* srcs = &g_srcs[fo.x];

    float acc = 0.0f;
    for (int i = lane; i < fo.y; i += 4)
        acc += g_p[srcs[i]];
    acc += __shfl_xor_sync(0xffffffffu, acc, 1);
    acc += __shfl_xor_sync(0xffffffffu, acc, 2);

    if (lane == 0) {
        float dinv = rsqrtf((float)(fo.y + 1));
        g_n1[n] = make_float2((acc + g_p[n]) * dinv, dinv);
    }
}

// Layer 2, 4 lanes/node: gather {agg1,dinv} (8B/edge), recompute
// q[j] = relu(agg1*W1[j]+b1[j])*dinv, accumulate 16-wide; butterfly;
// W2 + relu + Wfc head split across lanes.
__global__ void k_layer2out(const float* __restrict__ W1, const float* __restrict__ b1,
                            const float* __restrict__ W2, const float* __restrict__ b2,
                            const float* __restrict__ Wfc, const float* __restrict__ bfc,
                            float* __restrict__ out, int N) {
    __shared__ float sW1[16], sb1[16], sW2[256], sb2[16], sWfc[64], sbfc[4];
    int t = threadIdx.x;
    if (t < 16) { sW1[t] = W1[t]; sb1[t] = b1[t]; sb2[t] = b2[t]; }
    if (t < 256) sW2[t] = W2[t];
    if (t < 64)  sWfc[t] = Wfc[t];
    if (t < 4)   sbfc[t] = bfc[t];
    __syncthreads();

    int n = blockIdx.x * (blockDim.x >> 2) + (t >> 2);
    int lane = t & 3;
    if (n >= N) return;
    int2 fo = g_nfo[n];
    const int* srcs = &g_srcs[fo.x];

    float a16[16];
    #pragma unroll
    for (int j = 0; j < 16; j++) a16[j] = 0.0f;

    float2 self = g_n1[n];
    if (lane == 0) {
        #pragma unroll
        for (int j = 0; j < 16; j++)
            a16[j] += fmaxf(fmaf(self.x, sW1[j], sb1[j]), 0.0f) * self.y;
    }
    for (int i = lane; i < fo.y; i += 4) {
        float2 nr = g_n1[srcs[i]];
        #pragma unroll
        for (int j = 0; j < 16; j++)
            a16[j] += fmaxf(fmaf(nr.x, sW1[j], sb1[j]), 0.0f) * nr.y;
    }

    // butterfly across the 4 lanes: all lanes get the full 16-sum
    #pragma unroll
    for (int j = 0; j < 16; j++) {
        a16[j] += __shfl_xor_sync(0xffffffffu, a16[j], 1);
        a16[j] += __shfl_xor_sync(0xffffffffu, a16[j], 2);
    }

    float dn = self.y;
    // each lane: 4 of the 16 hidden features
    float h[4];
    #pragma unroll
    for (int j = 0; j < 4; j++) {
        int f = lane * 4 + j;
        float v = 0.0f;
        #pragma unroll
        for (int k = 0; k < 16; k++)
            v = fmaf(a16[k], sW2[k * 16 + f], v);
        h[j] = fmaxf(fmaf(v, dn, sb2[f]), 0.0f);
    }

    // partial class scores; butterfly; lane c writes out[4n+c]
    float oc[4];
    #pragma unroll
    for (int c = 0; c < 4; c++) {
        float v = 0.0f;
        #pragma unroll
        for (int j = 0; j < 4; j++)
            v = fmaf(h[j], sWfc[(lane * 4 + j) * 4 + c], v);
        oc[c] = v;
    }
    #pragma unroll
    for (int c = 0; c < 4; c++) {
        oc[c] += __shfl_xor_sync(0xffffffffu, oc[c], 1);
        oc[c] += __shfl_xor_sync(0xffffffffu, oc[c], 2);
    }
    out[4 * n + lane] = oc[lane] + sbfc[lane];
}

extern "C" void kernel_launch(void* const* d_in, const int* in_sizes, int n_in,
                              void* d_out, int out_size) {
    const float* x   = (const float*)d_in[0];
    const int*   ei  = (const int*)d_in[1];   // int32 (JAX x64 disabled)
    const float* W1  = (const float*)d_in[2];
    const float* b1  = (const float*)d_in[3];
    const float* W2  = (const float*)d_in[4];
    const float* b2  = (const float*)d_in[5];
    const float* Wfc = (const float*)d_in[6];
    const float* bfc = (const float*)d_in[7];
    (void)n_in; (void)out_size;

    int N  = in_sizes[0];       // 250000
    int E  = in_sizes[1] / 2;   // 4000000
    int E4 = E / 4;
    const int4* row4 = (const int4*)ei;
    const int4* col4 = (const int4*)(ei + E);

    int nbE4 = (E4 + 255) / 256;
    int nbN4 = (N + 63) / 64;   // 4 lanes/node, 256 threads/block
    int smB  = (2080 + CAPB) * (int)sizeof(int);  // ~90 KB dynamic smem

    static bool attr_done = false;
    if (!attr_done) {  // idempotent attribute set (not a stream op / alloc)
        cudaFuncSetAttribute(k_passB, cudaFuncAttributeMaxDynamicSharedMemorySize, smB);
        attr_done = true;
    }

    k_init<<<1, 256>>>();
    k_passA<<<nbE4, 256>>>(row4, col4, E4);
    k_passB<<<NB, 1024, smB>>>(x, N);
    k_layer1<<<nbN4, 256>>>(N);
    k_layer2out<<<nbN4, 256>>>(W1, b1, W2, b2, Wfc, bfc, (float*)d_out, N);
}

// round 10
// speedup vs baseline: 1.0009x; 1.0009x over previous
#include <cuda_runtime.h>

// GCN: 250K nodes, 4M edges, F 1->16->16->4. edge_index is int32.
// Bucketed counting-sort CSR build + register-recompute layer 2:
//   k_init  : zero 245 bucket cursors
//   k_passA : scatter (row,col) 8B/edge into coarse bucket col>>10
//             (hot per-bucket atomics are L2-aggregated => ~1 random op/edge)
//   k_passB : one block per bucket: smem histogram over 1024 local targets,
//             smem scan, smem place, coalesced CSR copy-out; also writes
//             per-node {start,deg} and p = x * rsqrt(deg+1)
//   k_layer1: 4 lanes/node gather p -> g_n1 = {agg1, dinv}
//   k_layer2: 4 lanes/node gather float2 {agg1,dinv} (8B/edge) and recompute
//             q[j] = relu(agg1*W1[j]+b1[j])*dinv in registers; W2/Wfc head
//             butterfly-reduced across the 4 lanes.

static constexpr int NN    = 250000;
static constexpr int BSH   = 10;                  // bucket = col >> 10
static constexpr int BNODE = 1 << BSH;            // 1024 nodes per bucket
static constexpr int NB    = (NN + BNODE - 1) / BNODE;   // 245
static constexpr int CAPB  = 20480;               // bucket capacity (mean 16384, +32 sigma)

__device__ int    g_bcnt[NB];           // bucket cursors
__device__ int2   g_bkt[NB * CAPB];     // staged edges (row, col) per bucket
__device__ int    g_srcs[NB * CAPB];    // CSR source ids (coalesced-written)
__device__ int2   g_nfo[NN];            // per node {start, deg}
__device__ float  g_p[NN];              // x * dinv
__device__ float2 g_n1[NN];             // {agg1, dinv}

__global__ void k_init() {
    int t = blockIdx.x * blockDim.x + threadIdx.x;
    if (t < NB) g_bcnt[t] = 0;
}

// Coarse scatter: 4 edges/thread. One random 8B store per edge; cursor
// atomics hit only 245 hot addresses (cheap, L2-aggregated).
__global__ void k_passA(const int4* __restrict__ row4,
                        const int4* __restrict__ col4, int E4) {
    int e = blockIdx.x * blockDim.x + threadIdx.x;
    if (e >= E4) return;
    int4 r = row4[e];
    int4 c = col4[e];
    int b0 = c.x >> BSH, b1 = c.y >> BSH, b2 = c.z >> BSH, b3 = c.w >> BSH;
    int p0 = atomicAdd(&g_bcnt[b0], 1);
    int p1 = atomicAdd(&g_bcnt[b1], 1);
    int p2 = atomicAdd(&g_bcnt[b2], 1);
    int p3 = atomicAdd(&g_bcnt[b3], 1);
    if (p0 < CAPB) g_bkt[b0 * CAPB + p0] = make_int2(r.x, c.x);
    if (p1 < CAPB) g_bkt[b1 * CAPB + p1] = make_int2(r.y, c.y);
    if (p2 < CAPB) g_bkt[b2 * CAPB + p2] = make_int2(r.z, c.z);
    if (p3 < CAPB) g_bkt[b3 * CAPB + p3] = make_int2(r.w, c.w);
}

// Per-bucket CSR build entirely in smem. blockDim = 1024, gridDim = NB.
// dyn smem: s_deg[1024] | s_off[1024] | s_wsum[32] | s_src[CAPB]
__global__ void k_passB(const float* __restrict__ x, int N) {
    extern __shared__ int sm[];
    int* s_deg  = sm;
    int* s_off  = sm + 1024;
    int* s_wsum = sm + 2048;
    int* s_src  = sm + 2080;

    int b  = blockIdx.x;
    int t  = threadIdx.x;
    int n0 = b << BSH;
    int cb = min(g_bcnt[b], CAPB);
    const int2* bkt = &g_bkt[b * CAPB];

    s_deg[t] = 0;
    __syncthreads();

    // histogram over local targets
    for (int i = t; i < cb; i += 1024)
        atomicAdd(&s_deg[bkt[i].y & (BNODE - 1)], 1);
    __syncthreads();

    // exclusive scan of s_deg (1024 = 32 warps x 32 lanes)
    int v = s_deg[t];
    int lane = t & 31;
    int incl = v;
    #pragma unroll
    for (int d = 1; d < 32; d <<= 1) {
        int u = __shfl_up_sync(0xffffffffu, incl, d);
        if (lane >= d) incl += u;
    }
    if (lane == 31) s_wsum[t >> 5] = incl;
    __syncthreads();
    if (t < 32) {
        int w = s_wsum[t];
        int wi = w;
        #pragma unroll
        for (int d = 1; d < 32; d <<= 1) {
            int u = __shfl_up_sync(0xffffffffu, wi, d);
            if (t >= d) wi += u;
        }
        s_wsum[t] = wi - w;  // exclusive
    }
    __syncthreads();
    int excl = incl - v + s_wsum[t >> 5];
    s_off[t] = excl;

    // per-node metadata + p (before s_off is consumed as a cursor)
    int n = n0 + t;
    if (n < N) {
        g_nfo[n] = make_int2(b * CAPB + excl, v);
        g_p[n] = x[n] * rsqrtf((float)(v + 1));
    }
    __syncthreads();

    // place into smem (s_off doubles as cursor), then coalesced copy-out
    for (int i = t; i < cb; i += 1024) {
        int2 e = bkt[i];
        int pos = atomicAdd(&s_off[e.y & (BNODE - 1)], 1);
        s_src[pos] = e.x;
    }
    __syncthreads();
    int* dst = &g_srcs[b * CAPB];
    for (int i = t; i < cb; i += 1024)
        dst[i] = s_src[i];
}

// Layer 1, 4 lanes/node: agg1 = dinv*(p[n] + sum p[neigh]); store {agg1,dinv}.
__global__ void k_layer1(int N) {
    int t = threadIdx.x;
    int n = blockIdx.x * (blockDim.x >> 2) + (t >> 2);
    int lane = t & 3;
    if (n >= N) return;
    int2 fo = g_nfo[n];
    const int* srcs = &g_srcs[fo.x];

    float acc = 0.0f;
    for (int i = lane; i < fo.y; i += 4)
        acc += g_p[srcs[i]];
    acc += __shfl_xor_sync(0xffffffffu, acc, 1);
    acc += __shfl_xor_sync(0xffffffffu, acc, 2);

    if (lane == 0) {
        float dinv = rsqrtf((float)(fo.y + 1));
        g_n1[n] = make_float2((acc + g_p[n]) * dinv, dinv);
    }
}

// Layer 2, 4 lanes/node: gather {agg1,dinv} (8B/edge), recompute
// q[j] = relu(agg1*W1[j]+b1[j])*dinv, accumulate 16-wide; butterfly;
// W2 + relu + Wfc head split across lanes.
__global__ void k_layer2out(const float* __restrict__ W1, const float* __restrict__ b1,
                            const float* __restrict__ W2, const float* __restrict__ b2,
                            const float* __restrict__ Wfc, const float* __restrict__ bfc,
                            float* __restrict__ out, int N) {
    __shared__ float sW1[16], sb1[16], sW2[256], sb2[16], sWfc[64], sbfc[4];
    int t = threadIdx.x;
    if (t < 16) { sW1[t] = W1[t]; sb1[t] = b1[t]; sb2[t] = b2[t]; }
    if (t < 256) sW2[t] = W2[t];
    if (t < 64)  sWfc[t] = Wfc[t];
    if (t < 4)   sbfc[t] = bfc[t];
    __syncthreads();

    int n = blockIdx.x * (blockDim.x >> 2) + (t >> 2);
    int lane = t & 3;
    if (n >= N) return;
    int2 fo = g_nfo[n];
    const int* srcs = &g_srcs[fo.x];

    float a16[16];
    #pragma unroll
    for (int j = 0; j < 16; j++) a16[j] = 0.0f;

    float2 self = g_n1[n];
    if (lane == 0) {
        #pragma unroll
        for (int j = 0; j < 16; j++)
            a16[j] += fmaxf(fmaf(self.x, sW1[j], sb1[j]), 0.0f) * self.y;
    }
    for (int i = lane; i < fo.y; i += 4) {
        float2 nr = g_n1[srcs[i]];
        #pragma unroll
        for (int j = 0; j < 16; j++)
            a16[j] += fmaxf(fmaf(nr.x, sW1[j], sb1[j]), 0.0f) * nr.y;
    }

    // butterfly across the 4 lanes: all lanes get the full 16-sum
    #pragma unroll
    for (int j = 0; j < 16; j++) {
        a16[j] += __shfl_xor_sync(0xffffffffu, a16[j], 1);
        a16[j] += __shfl_xor_sync(0xffffffffu, a16[j], 2);
    }

    float dn = self.y;
    // each lane: 4 of the 16 hidden features
    float h[4];
    #pragma unroll
    for (int j = 0; j < 4; j++) {
        int f = lane * 4 + j;
        float v = 0.0f;
        #pragma unroll
        for (int k = 0; k < 16; k++)
            v = fmaf(a16[k], sW2[k * 16 + f], v);
        h[j] = fmaxf(fmaf(v, dn, sb2[f]), 0.0f);
    }

    // partial class scores; butterfly; lane c writes out[4n+c]
    float oc[4];
    #pragma unroll
    for (int c = 0; c < 4; c++) {
        float v = 0.0f;
        #pragma unroll
        for (int j = 0; j < 4; j++)
            v = fmaf(h[j], sWfc[(lane * 4 + j) * 4 + c], v);
        oc[c] = v;
    }
    #pragma unroll
    for (int c = 0; c < 4; c++) {
        oc[c] += __shfl_xor_sync(0xffffffffu, oc[c], 1);
        oc[c] += __shfl_xor_sync(0xffffffffu, oc[c], 2);
    }
    out[4 * n + lane] = oc[lane] + sbfc[lane];
}

extern "C" void kernel_launch(void* const* d_in, const int* in_sizes, int n_in,
                              void* d_out, int out_size) {
    const float* x   = (const float*)d_in[0];
    const int*   ei  = (const int*)d_in[1];   // int32 (JAX x64 disabled)
    const float* W1  = (const float*)d_in[2];
    const float* b1  = (const float*)d_in[3];
    const float* W2  = (const float*)d_in[4];
    const float* b2  = (const float*)d_in[5];
    const float* Wfc = (const float*)d_in[6];
    const float* bfc = (const float*)d_in[7];
    (void)n_in; (void)out_size;

    int N  = in_sizes[0];       // 250000
    int E  = in_sizes[1] / 2;   // 4000000
    int E4 = E / 4;
    const int4* row4 = (const int4*)ei;
    const int4* col4 = (const int4*)(ei + E);

    int nbE4 = (E4 + 255) / 256;
    int nbN4 = (N + 63) / 64;   // 4 lanes/node, 256 threads/block
    int smB  = (2080 + CAPB) * (int)sizeof(int);  // ~90 KB dynamic smem

    static bool attr_done = false;
    if (!attr_done) {  // idempotent attribute set (not a stream op / alloc)
        cudaFuncSetAttribute(k_passB, cudaFuncAttributeMaxDynamicSharedMemorySize, smB);
        attr_done = true;
    }

    k_init<<<1, 256>>>();
    k_passA<<<nbE4, 256>>>(row4, col4, E4);
    k_passB<<<NB, 1024, smB>>>(x, N);
    k_layer1<<<nbN4, 256>>>(N);
    k_layer2out<<<nbN4, 256>>>(W1, b1, W2, b2, Wfc, bfc, (float*)d_out, N);
}

// round 11
// speedup vs baseline: 8.7757x; 8.7675x over previous
#include <cuda_runtime.h>

// GCN: 250K nodes, 4M edges, F 1->16->16->4. edge_index is int32.
// Fixed-capacity CSR (64 slots/node; Poisson(16) => overflow prob ~1e-18).
// Scattered per-node atomics (250K addresses, ~16 ops each) are the FAST
// regime on B300's LTS; hot-bucket return-atomics (round 10) serialized.
//   k_init     : zero per-node counters
//   k_place    : pos=atomicAdd(cnt[col]); srcs[col*64+pos]=row (4 edges/thread)
//   k_prep     : dinv = rsqrt(cnt+1), p = x*dinv
//   k_layer1   : 4 lanes/node gather p -> g_n1 = {agg1, dinv}
//   k_layer2out: 4 lanes/node gather float2 {agg1,dinv} (8B/edge), recompute
//                q[j] = relu(agg1*W1[j]+b1[j])*dinv in registers; W2/Wfc head
//                butterfly-reduced across the 4 lanes.

static constexpr int NN  = 250000;
static constexpr int CAP = 64;

__device__ int    g_cnt[NN];        // degree (excl self-loop), also fill cursor
__device__ float  g_p[NN];          // x * dinv
__device__ float2 g_n1[NN];         // {agg1, dinv}
__device__ int    g_srcs[NN * CAP]; // fixed-capacity bins (64MB)

__global__ void k_init(int N) {
    int n = blockIdx.x * blockDim.x + threadIdx.x;
    if (n < N) g_cnt[n] = 0;
}

// Single-pass CSR build: 4 edges per thread via int4.
__global__ void k_place(const int4* __restrict__ row4,
                        const int4* __restrict__ col4, int E4) {
    int e = blockIdx.x * blockDim.x + threadIdx.x;
    if (e >= E4) return;
    int4 r = row4[e];
    int4 c = col4[e];
    int p0 = atomicAdd(&g_cnt[c.x], 1);
    int p1 = atomicAdd(&g_cnt[c.y], 1);
    int p2 = atomicAdd(&g_cnt[c.z], 1);
    int p3 = atomicAdd(&g_cnt[c.w], 1);
    if (p0 < CAP) g_srcs[c.x * CAP + p0] = r.x;
    if (p1 < CAP) g_srcs[c.y * CAP + p1] = r.y;
    if (p2 < CAP) g_srcs[c.z * CAP + p2] = r.z;
    if (p3 < CAP) g_srcs[c.w * CAP + p3] = r.w;
}

__global__ void k_prep(const float* __restrict__ x, int N) {
    int n = blockIdx.x * blockDim.x + threadIdx.x;
    if (n >= N) return;
    int cnt = g_cnt[n];                       // true degree (unclamped)
    float dinv = rsqrtf((float)(cnt + 1));
    g_p[n] = x[n] * dinv;
}

// Layer 1, 4 lanes/node: agg1 = dinv*(p[n] + sum p[neigh]); store {agg1,dinv}.
__global__ void k_layer1(int N) {
    int t = threadIdx.x;
    int n = blockIdx.x * (blockDim.x >> 2) + (t >> 2);
    int lane = t & 3;
    if (n >= N) return;
    int cntT = g_cnt[n];
    int cnt = min(cntT, CAP);
    const int* srcs = &g_srcs[n * CAP];

    float acc = 0.0f;
    for (int i = lane; i < cnt; i += 4)
        acc += g_p[srcs[i]];
    acc += __shfl_xor_sync(0xffffffffu, acc, 1);
    acc += __shfl_xor_sync(0xffffffffu, acc, 2);

    if (lane == 0) {
        float dinv = rsqrtf((float)(cntT + 1));
        g_n1[n] = make_float2((acc + g_p[n]) * dinv, dinv);
    }
}

// Layer 2, 4 lanes/node: gather {agg1,dinv} (8B/edge); recompute
// q[j] = relu(agg1*W1[j]+b1[j])*dinv in registers, accumulate 16-wide;
// butterfly; W2 + relu + Wfc head split across lanes.
__global__ void k_layer2out(const float* __restrict__ W1, const float* __restrict__ b1,
                            const float* __restrict__ W2, const float* __restrict__ b2,
                            const float* __restrict__ Wfc, const float* __restrict__ bfc,
                            float* __restrict__ out, int N) {
    __shared__ float sW1[16], sb1[16], sW2[256], sb2[16], sWfc[64], sbfc[4];
    int t = threadIdx.x;
    if (t < 16) { sW1[t] = W1[t]; sb1[t] = b1[t]; sb2[t] = b2[t]; }
    if (t < 256) sW2[t] = W2[t];
    if (t < 64)  sWfc[t] = Wfc[t];
    if (t < 4)   sbfc[t] = bfc[t];
    __syncthreads();

    int n = blockIdx.x * (blockDim.x >> 2) + (t >> 2);
    int lane = t & 3;
    if (n >= N) return;
    int cnt = min(g_cnt[n], CAP);
    const int* srcs = &g_srcs[n * CAP];

    float a16[16];
    #pragma unroll
    for (int j = 0; j < 16; j++) a16[j] = 0.0f;

    float2 self = g_n1[n];
    if (lane == 0) {
        #pragma unroll
        for (int j = 0; j < 16; j++)
            a16[j] += fmaxf(fmaf(self.x, sW1[j], sb1[j]), 0.0f) * self.y;
    }
    for (int i = lane; i < cnt; i += 4) {
        float2 nr = g_n1[srcs[i]];
        #pragma unroll
        for (int j = 0; j < 16; j++)
            a16[j] += fmaxf(fmaf(nr.x, sW1[j], sb1[j]), 0.0f) * nr.y;
    }

    // butterfly across the 4 lanes: all lanes get the full 16-sum
    #pragma unroll
    for (int j = 0; j < 16; j++) {
        a16[j] += __shfl_xor_sync(0xffffffffu, a16[j], 1);
        a16[j] += __shfl_xor_sync(0xffffffffu, a16[j], 2);
    }

    float dn = self.y;
    // each lane: 4 of the 16 hidden features
    float h[4];
    #pragma unroll
    for (int j = 0; j < 4; j++) {
        int f = lane * 4 + j;
        float v = 0.0f;
        #pragma unroll
        for (int k = 0; k < 16; k++)
            v = fmaf(a16[k], sW2[k * 16 + f], v);
        h[j] = fmaxf(fmaf(v, dn, sb2[f]), 0.0f);
    }

    // partial class scores; butterfly; lane c writes out[4n+c]
    float oc[4];
    #pragma unroll
    for (int c = 0; c < 4; c++) {
        float v = 0.0f;
        #pragma unroll
        for (int j = 0; j < 4; j++)
            v = fmaf(h[j], sWfc[(lane * 4 + j) * 4 + c], v);
        oc[c] = v;
    }
    #pragma unroll
    for (int c = 0; c < 4; c++) {
        oc[c] += __shfl_xor_sync(0xffffffffu, oc[c], 1);
        oc[c] += __shfl_xor_sync(0xffffffffu, oc[c], 2);
    }
    out[4 * n + lane] = oc[lane] + sbfc[lane];
}

extern "C" void kernel_launch(void* const* d_in, const int* in_sizes, int n_in,
                              void* d_out, int out_size) {
    const float* x   = (const float*)d_in[0];
    const int*   ei  = (const int*)d_in[1];   // int32 (JAX x64 disabled)
    const float* W1  = (const float*)d_in[2];
    const float* b1  = (const float*)d_in[3];
    const float* W2  = (const float*)d_in[4];
    const float* b2  = (const float*)d_in[5];
    const float* Wfc = (const float*)d_in[6];
    const float* bfc = (const float*)d_in[7];
    (void)n_in; (void)out_size;

    int N  = in_sizes[0];       // 250000
    int E  = in_sizes[1] / 2;   // 4000000
    int E4 = E / 4;
    const int4* row4 = (const int4*)ei;
    const int4* col4 = (const int4*)(ei + E);

    int nbN  = (N + 255) / 256;
    int nbE4 = (E4 + 255) / 256;
    int nbN4 = (N + 63) / 64;   // 4 lanes/node, 256 threads/block

    k_init<<<nbN, 256>>>(N);
    k_place<<<nbE4, 256>>>(row4, col4, E4);
    k_prep<<<nbN, 256>>>(x, N);
    k_layer1<<<nbN4, 256>>>(N);
    k_layer2out<<<nbN4, 256>>>(W1, b1, W2, b2, Wfc, bfc, (float*)d_out, N);
}